// round 2
// baseline (speedup 1.0000x reference)
#include <cuda_runtime.h>
#include <cstdint>

// ---------------------------------------------------------------------------
// SSIM + L1 fused loss, GB300 sm_103a — round 2: packed f32x2 math.
// Each thread computes TWO output columns (t and t+64) with all arithmetic in
// fma.rn.f32x2 / mul.rn.f32x2 / add.rn.f32x2 (128-lane FP32 pipe).
// SMEM tiles hold pre-packed (x[c], x[c+64]) pairs so both columns share the
// same 9-tap shifted window (one LDS.64 per tap per map).
// ---------------------------------------------------------------------------

#define IW 1024
#define IH 1024
#define OW 1016
#define OH 1016
#define NIMG 32
#define TW 128            // output columns per block
#define TH 32             // output rows per block
#define HALO 8
#define THREADS 64        // 2 columns per thread
#define TILE_H (TH + HALO)            // 40
#define PW (TW / 2 + HALO)            // 72 packed entries per row
#define ROWF (TW + HALO)              // 136 floats loaded per row per map

typedef unsigned long long u64;

// Gaussian taps, sigma=1.5, normalized (exact separable form of reference w).
constexpr double E0 = 0.02856550;
constexpr double E1 = 0.13533528;
constexpr double E2 = 0.41111229;
constexpr double E3 = 0.80073740;
constexpr double GS = 1.0 + 2.0 * (E0 + E1 + E2 + E3);

__device__ constexpr float G[9] = {
    (float)(E0 / GS), (float)(E1 / GS), (float)(E2 / GS), (float)(E3 / GS),
    (float)(1.0 / GS),
    (float)(E3 / GS), (float)(E2 / GS), (float)(E1 / GS), (float)(E0 / GS)
};

// ---- packed f32x2 helpers -------------------------------------------------
__device__ __forceinline__ u64 pk(float a, float b) {
    u64 d; asm("mov.b64 %0, {%1, %2};" : "=l"(d) : "f"(a), "f"(b)); return d;
}
__device__ __forceinline__ float2 unpk(u64 d) {
    float2 r; asm("mov.b64 {%0, %1}, %2;" : "=f"(r.x), "=f"(r.y) : "l"(d)); return r;
}
__device__ __forceinline__ u64 ffma2(u64 a, u64 b, u64 c) {
    u64 d; asm("fma.rn.f32x2 %0, %1, %2, %3;" : "=l"(d) : "l"(a), "l"(b), "l"(c)); return d;
}
__device__ __forceinline__ u64 fmul2(u64 a, u64 b) {
    u64 d; asm("mul.rn.f32x2 %0, %1, %2;" : "=l"(d) : "l"(a), "l"(b)); return d;
}
__device__ __forceinline__ u64 fadd2(u64 a, u64 b) {
    u64 d; asm("add.rn.f32x2 %0, %1, %2;" : "=l"(d) : "l"(a), "l"(b)); return d;
}
#define SGN2 0x8000000080000000ULL

__device__ double g_acc[2];  // [0] = sum(1 - S), [1] = sum |x-y|

__global__ void ssim_init_kernel() { g_acc[0] = 0.0; g_acc[1] = 0.0; }

__global__ __launch_bounds__(THREADS) void ssim_main_kernel(
    const float* __restrict__ X, const float* __restrict__ Y) {
    // Packed tiles: entry [r][i] = (x[r][i], x[r][i+64]).  2 * 40*72*8 = 45 KB.
    __shared__ u64 tile_x[TILE_H][PW];
    __shared__ u64 tile_y[TILE_H][PW];

    const int tx  = blockIdx.x;   // 0..7
    const int ty  = blockIdx.y;   // 0..31
    const int img = blockIdx.z;   // 0..31
    const int ix0 = tx * TW;
    const int iy0 = ty * TH;
    const size_t base = (size_t)img * IW * IH;
    const float* __restrict__ Xi = X + base;
    const float* __restrict__ Yi = Y + base;
    const int tid = threadIdx.x;

    // ---- Load tile (float2 vectorized), build packed layout, own L1 -------
    float l1 = 0.f;
    float* fx = (float*)&tile_x[0][0];   // entry e: lo at 2e, hi at 2e+1
    float* fy = (float*)&tile_y[0][0];
    #pragma unroll 2
    for (int idx = tid; idx < TILE_H * (ROWF / 2); idx += THREADS) {
        int ly = idx / (ROWF / 2);
        int l  = (idx - ly * (ROWF / 2)) * 2;       // even local col 0..134
        int gy = iy0 + ly;
        int gx = ix0 + l;
        float2 xv = make_float2(0.f, 0.f), yv = xv;
        if (gy < IH && gx + 1 < IW) {               // pairs never straddle edge
            xv = *(const float2*)(Xi + (size_t)gy * IW + gx);
            yv = *(const float2*)(Yi + (size_t)gy * IW + gx);
        }
        if (ly < TH && l < TW)                      // exclusive region: l, l+1 < 128
            l1 += fabsf(xv.x - yv.x) + fabsf(xv.y - yv.y);
        int rb = ly * (2 * PW);
        // element l
        if (l < PW)  { fx[rb + 2 * l] = xv.x;            fy[rb + 2 * l] = yv.x; }
        if (l >= 64) { fx[rb + 2 * (l - 64) + 1] = xv.x; fy[rb + 2 * (l - 64) + 1] = yv.x; }
        int m = l + 1;
        if (m < PW)  { fx[rb + 2 * m] = xv.y;            fy[rb + 2 * m] = yv.y; }
        if (m >= 64) { fx[rb + 2 * (m - 64) + 1] = xv.y; fy[rb + 2 * (m - 64) + 1] = yv.y; }
    }
    __syncthreads();

    // ---- packed constants --------------------------------------------------
    u64 G2[9];
    #pragma unroll
    for (int k = 0; k < 9; ++k) G2[k] = pk(G[k], G[k]);
    const u64 TWO2 = pk(2.f, 2.f);
    const u64 C1p  = pk(0.0004f, 0.0004f);
    const u64 C2p  = pk(0.0036f, 0.0036f);

    const int  lane      = tid;                       // column pair (lane, lane+64)
    const bool col1valid = (ix0 + lane + 64) < OW;    // col0 always < OW
    const int  nrows     = (iy0 + TH <= OH) ? TH : (OH - iy0);

    // Vertical ring accumulators (packed): 45 u64 = 90 regs.
    u64 ax[9] = {}, ay[9] = {}, axx[9] = {}, ayy[9] = {}, axy[9] = {};
    float ssim = 0.f;

    #pragma unroll
    for (int r = 0; r < TILE_H; ++r) {
        // Horizontal 9-tap conv, 5 maps, 2 columns per op.
        u64 hx = 0, hy = 0, hxx = 0, hyy = 0, hxy = 0;
        const u64* rx = &tile_x[r][lane];
        const u64* ry = &tile_y[r][lane];
        #pragma unroll
        for (int k = 0; k < 9; ++k) {
            u64 px = rx[k];
            u64 py = ry[k];
            u64 g2 = G2[k];
            hx  = ffma2(g2, px, hx);
            hy  = ffma2(g2, py, hy);
            u64 gx = fmul2(g2, px);
            u64 gy = fmul2(g2, py);
            hxx = ffma2(gx, px, hxx);
            hyy = ffma2(gy, py, hyy);
            hxy = ffma2(gx, py, hxy);
        }
        // Scatter into vertical ring (indices constant-folded).
        #pragma unroll
        for (int j = 0; j < 9; ++j) {
            int o = r - j;
            if (o < 0 || o >= TH) continue;
            int s = o % 9;
            u64 g2 = G2[j];
            ax [s] = ffma2(g2, hx,  ax [s]);
            ay [s] = ffma2(g2, hy,  ay [s]);
            axx[s] = ffma2(g2, hxx, axx[s]);
            ayy[s] = ffma2(g2, hyy, ayy[s]);
            axy[s] = ffma2(g2, hxy, axy[s]);
        }
        // Output row (r - 8) complete.
        if (r >= HALO) {
            int o = r - HALO;
            int s = o % 9;
            u64 ux = ax[s], uy = ay[s], uxx = axx[s], uyy = ayy[s], uxy = axy[s];
            ax[s] = 0; ay[s] = 0; axx[s] = 0; ayy[s] = 0; axy[s] = 0;
            if (o < nrows) {
                u64 nux = ux ^ SGN2;
                u64 nuy = uy ^ SGN2;
                u64 vx  = ffma2(nux, ux, uxx);        // uxx - ux*ux
                u64 vy  = ffma2(nuy, uy, uyy);
                u64 vxy = ffma2(nux, uy, uxy);        // uxy - ux*uy
                u64 A1  = ffma2(TWO2, fmul2(ux, uy), C1p);
                u64 A2  = ffma2(TWO2, vxy, C2p);
                u64 B1  = ffma2(ux, ux, ffma2(uy, uy, C1p));
                u64 B2  = fadd2(fadd2(vx, vy), C2p);
                float2 num = unpk(fmul2(A1, A2));
                float2 den = unpk(fmul2(B1, B2));
                ssim += 1.f - __fdividef(num.x, den.x);
                if (col1valid)
                    ssim += 1.f - __fdividef(num.y, den.y);
            }
        }
    }

    // ---- Block reduction (2 warps), one double atomic pair per block ------
    #pragma unroll
    for (int off = 16; off; off >>= 1) {
        ssim += __shfl_down_sync(0xffffffffu, ssim, off);
        l1   += __shfl_down_sync(0xffffffffu, l1,   off);
    }
    __shared__ float red[2][THREADS / 32];
    int w = tid >> 5;
    if ((tid & 31) == 0) { red[0][w] = ssim; red[1][w] = l1; }
    __syncthreads();
    if (tid == 0) {
        float s = 0.f, l = 0.f;
        #pragma unroll
        for (int i = 0; i < THREADS / 32; ++i) { s += red[0][i]; l += red[1][i]; }
        atomicAdd(&g_acc[0], (double)s);
        atomicAdd(&g_acc[1], (double)l);
    }
}

__global__ void ssim_finish_kernel(float* __restrict__ out) {
    double ssim_mean = g_acc[0] / ((double)NIMG * OW * OH);
    double l1_mean   = g_acc[1] / ((double)NIMG * IW * IH);
    out[0] = (float)(0.5 * ssim_mean + 1.0 * l1_mean);
}

extern "C" void kernel_launch(void* const* d_in, const int* in_sizes, int n_in,
                              void* d_out, int out_size) {
    const float* X = (const float*)d_in[0];
    const float* Y = (const float*)d_in[1];
    (void)in_sizes; (void)n_in; (void)out_size;

    ssim_init_kernel<<<1, 1>>>();
    dim3 grid(IW / TW, IH / TH, NIMG);  // (8, 32, 32) = 8192 blocks
    ssim_main_kernel<<<grid, THREADS>>>(X, Y);
    ssim_finish_kernel<<<1, 1>>>((float*)d_out);
}

// round 3
// speedup vs baseline: 1.1413x; 1.1413x over previous
#include <cuda_runtime.h>
#include <cstdint>

// ---------------------------------------------------------------------------
// SSIM + L1 fused loss, GB300 sm_103a — round 3.
// Back to SCALAR math (round-2 f32x2 regressed 2x: it forfeited the rt=1
// immediate-FFMA path). New: precompute x^2, y^2, x*y once per input element
// into SMEM, so the 5-map horizontal conv is pure immediate-form FFMA
// (rt_SMSP=1) + 2 LDS per tap. Vertical ring conv already pure imm-FFMA.
// Ring indices constant-folded via period-9 loop structure (small I$ footprint).
// ---------------------------------------------------------------------------

#define IW 1024
#define IH 1024
#define OW 1016
#define OH 1016
#define NIMG 32
#define TW 128            // output columns per block
#define TH 32             // output rows per block
#define HALO 8
#define THREADS 128
#define TILE_W (TW + HALO)            // 136
#define TILE_H (TH + HALO)            // 40

// Dynamic SMEM: float4 tile {x, y, x*x, y*y} + float tile {x*y}
#define SMEM_BYTES (TILE_H * TILE_W * 16 + TILE_H * TILE_W * 4)   // 108800

// Gaussian taps, sigma=1.5, normalized (exact separable form of reference w).
constexpr double E0 = 0.02856550;   // exp(-32/9)
constexpr double E1 = 0.13533528;   // exp(-2)
constexpr double E2 = 0.41111229;   // exp(-8/9)
constexpr double E3 = 0.80073740;   // exp(-2/9)
constexpr double GS = 1.0 + 2.0 * (E0 + E1 + E2 + E3);

__device__ constexpr float G[9] = {
    (float)(E0 / GS), (float)(E1 / GS), (float)(E2 / GS), (float)(E3 / GS),
    (float)(1.0 / GS),
    (float)(E3 / GS), (float)(E2 / GS), (float)(E1 / GS), (float)(E0 / GS)
};

__device__ double g_acc[2];  // [0] = sum(1 - S), [1] = sum |x-y|

__global__ void ssim_init_kernel() { g_acc[0] = 0.0; g_acc[1] = 0.0; }

struct Ring {
    float ax[9], ay[9], axx[9], ayy[9], axy[9];
};

// One input row's work: horizontal conv (all imm-FFMA) + ring scatter + emit.
// RR = compile-time row phase (ring slot = (RR - j) mod 9 folds to constant).
// JMIN: skip taps with o = r - j < 0 (first 8 rows only).
template <int RR, int JMAX, bool EMIT>
__device__ __forceinline__ void row_step(
    const float4* __restrict__ row4, const float* __restrict__ rxy,
    Ring& A, float& ssim, int o_dyn, int emit_bound) {
    float hx = 0.f, hy = 0.f, hxx = 0.f, hyy = 0.f, hxy = 0.f;
    #pragma unroll
    for (int k = 0; k < 9; ++k) {
        float4 v = row4[k];
        float  g = G[k];
        hx  += g * v.x;
        hy  += g * v.y;
        hxx += g * v.z;
        hyy += g * v.w;
        hxy += g * rxy[k];
    }
    #pragma unroll
    for (int j = 0; j <= JMAX; ++j) {
        constexpr_slot:;
        int s = ((RR - j) % 9 + 9) % 9;    // compile-time constant
        float g = G[j];
        A.ax [s] += g * hx;
        A.ay [s] += g * hy;
        A.axx[s] += g * hxx;
        A.ayy[s] += g * hyy;
        A.axy[s] += g * hxy;
    }
    if (EMIT) {
        int s = ((RR - 8) % 9 + 9) % 9;    // slot of completed output row
        float ux = A.ax[s], uy = A.ay[s];
        float uxx = A.axx[s], uyy = A.ayy[s], uxy = A.axy[s];
        A.ax[s] = 0.f; A.ay[s] = 0.f; A.axx[s] = 0.f; A.ayy[s] = 0.f; A.axy[s] = 0.f;
        if (o_dyn < emit_bound) {
            constexpr float C1 = 0.0004f;  // (0.01*2)^2
            constexpr float C2 = 0.0036f;  // (0.03*2)^2
            float vx  = uxx - ux * ux;
            float vy  = uyy - uy * uy;
            float vxy = uxy - ux * uy;
            float A1v = 2.f * ux * uy + C1;
            float A2v = 2.f * vxy + C2;
            float B1v = ux * ux + uy * uy + C1;
            float B2v = vx + vy + C2;
            ssim += 1.f - __fdividef(A1v * A2v, B1v * B2v);
        }
    }
}

__global__ __launch_bounds__(THREADS) void ssim_main_kernel(
    const float* __restrict__ X, const float* __restrict__ Y) {
    extern __shared__ char smem_raw[];
    float4* t4  = (float4*)smem_raw;                                 // [40][136]
    float*  txy = (float*)(smem_raw + TILE_H * TILE_W * 16);         // [40][136]

    const int tx  = blockIdx.x;   // 0..7
    const int ty  = blockIdx.y;   // 0..31
    const int img = blockIdx.z;   // 0..31
    const int ix0 = tx * TW;
    const int iy0 = ty * TH;
    const size_t base = (size_t)img * IW * IH;
    const float* __restrict__ Xi = X + base;
    const float* __restrict__ Yi = Y + base;
    const int tid = threadIdx.x;

    // ---- Load tile, precompute squares/cross, own L1 ----------------------
    float l1 = 0.f;
    #pragma unroll 2
    for (int idx = tid; idx < TILE_H * (TILE_W / 2); idx += THREADS) {
        int ly = idx / (TILE_W / 2);
        int l  = (idx - ly * (TILE_W / 2)) * 2;     // even local col 0..134
        int gy = iy0 + ly;
        int gx = ix0 + l;
        float2 xv = make_float2(0.f, 0.f), yv = xv;
        if (gy < IH && gx + 1 < IW) {
            xv = *(const float2*)(Xi + (size_t)gy * IW + gx);
            yv = *(const float2*)(Yi + (size_t)gy * IW + gx);
        }
        if (ly < TH && l < TW)
            l1 += fabsf(xv.x - yv.x) + fabsf(xv.y - yv.y);
        int rb = ly * TILE_W;
        t4 [rb + l]     = make_float4(xv.x, yv.x, xv.x * xv.x, yv.x * yv.x);
        t4 [rb + l + 1] = make_float4(xv.y, yv.y, xv.y * xv.y, yv.y * yv.y);
        txy[rb + l]     = xv.x * yv.x;
        txy[rb + l + 1] = xv.y * yv.y;
    }
    __syncthreads();

    const int  lane     = tid;
    const bool colvalid = (ix0 + lane) < OW;
    const int  nrows    = (iy0 + TH <= OH) ? TH : (OH - iy0);
    const int  emit_bound = colvalid ? nrows : 0;

    Ring A;
    #pragma unroll
    for (int s = 0; s < 9; ++s) {
        A.ax[s] = 0.f; A.ay[s] = 0.f; A.axx[s] = 0.f; A.ayy[s] = 0.f; A.axy[s] = 0.f;
    }
    float ssim = 0.f;

    const float4* base4  = t4  + lane;
    const float*  basexy = txy + lane;

    // ---- rows 0..7: partial taps, no emission -----------------------------
    #pragma unroll
    for (int r = 0; r < 8; ++r) {
        // JMAX = r (taps j > r would reference negative output rows)
        switch (r) {  // keeps template instantiation per static r
            default: break;
        }
    }
    // (unrolled explicitly to keep RR/JMAX compile-time)
    row_step<0, 0, false>(base4 + 0 * TILE_W, basexy + 0 * TILE_W, A, ssim, 0, 0);
    row_step<1, 1, false>(base4 + 1 * TILE_W, basexy + 1 * TILE_W, A, ssim, 0, 0);
    row_step<2, 2, false>(base4 + 2 * TILE_W, basexy + 2 * TILE_W, A, ssim, 0, 0);
    row_step<3, 3, false>(base4 + 3 * TILE_W, basexy + 3 * TILE_W, A, ssim, 0, 0);
    row_step<4, 4, false>(base4 + 4 * TILE_W, basexy + 4 * TILE_W, A, ssim, 0, 0);
    row_step<5, 5, false>(base4 + 5 * TILE_W, basexy + 5 * TILE_W, A, ssim, 0, 0);
    row_step<6, 6, false>(base4 + 6 * TILE_W, basexy + 6 * TILE_W, A, ssim, 0, 0);
    row_step<7, 7, false>(base4 + 7 * TILE_W, basexy + 7 * TILE_W, A, ssim, 0, 0);
    // ---- row 8: first emission (o = 0) ------------------------------------
    row_step<8, 8, true>(base4 + 8 * TILE_W, basexy + 8 * TILE_W, A, ssim, 0, emit_bound);

    // ---- rows 9..35: three static 9-row bodies ----------------------------
    // For r = 9*(p+1) + rr, (r - j) % 9 == (rr - j) % 9: slots are static.
    for (int p = 0; p < 3; ++p) {
        const float4* pb4  = base4  + (9 * (p + 1)) * TILE_W;
        const float*  pbxy = basexy + (9 * (p + 1)) * TILE_W;
        const int     ob   = 9 * p + 1;         // o for rr = 0
        row_step<0, 8, true>(pb4 + 0 * TILE_W, pbxy + 0 * TILE_W, A, ssim, ob + 0, emit_bound);
        row_step<1, 8, true>(pb4 + 1 * TILE_W, pbxy + 1 * TILE_W, A, ssim, ob + 1, emit_bound);
        row_step<2, 8, true>(pb4 + 2 * TILE_W, pbxy + 2 * TILE_W, A, ssim, ob + 2, emit_bound);
        row_step<3, 8, true>(pb4 + 3 * TILE_W, pbxy + 3 * TILE_W, A, ssim, ob + 3, emit_bound);
        row_step<4, 8, true>(pb4 + 4 * TILE_W, pbxy + 4 * TILE_W, A, ssim, ob + 4, emit_bound);
        row_step<5, 8, true>(pb4 + 5 * TILE_W, pbxy + 5 * TILE_W, A, ssim, ob + 5, emit_bound);
        row_step<6, 8, true>(pb4 + 6 * TILE_W, pbxy + 6 * TILE_W, A, ssim, ob + 6, emit_bound);
        row_step<7, 8, true>(pb4 + 7 * TILE_W, pbxy + 7 * TILE_W, A, ssim, ob + 7, emit_bound);
        row_step<8, 8, true>(pb4 + 8 * TILE_W, pbxy + 8 * TILE_W, A, ssim, ob + 8, emit_bound);
    }

    // ---- rows 36..39 (r % 9 = 0..3), o = 28..31 ---------------------------
    row_step<0, 8, true>(base4 + 36 * TILE_W, basexy + 36 * TILE_W, A, ssim, 28, emit_bound);
    row_step<1, 8, true>(base4 + 37 * TILE_W, basexy + 37 * TILE_W, A, ssim, 29, emit_bound);
    row_step<2, 8, true>(base4 + 38 * TILE_W, basexy + 38 * TILE_W, A, ssim, 30, emit_bound);
    row_step<3, 8, true>(base4 + 39 * TILE_W, basexy + 39 * TILE_W, A, ssim, 31, emit_bound);

    // ---- Block reduction, one double atomic pair per block ----------------
    #pragma unroll
    for (int off = 16; off; off >>= 1) {
        ssim += __shfl_down_sync(0xffffffffu, ssim, off);
        l1   += __shfl_down_sync(0xffffffffu, l1,   off);
    }
    __shared__ float red[2][THREADS / 32];
    int w = tid >> 5;
    if ((tid & 31) == 0) { red[0][w] = ssim; red[1][w] = l1; }
    __syncthreads();
    if (tid == 0) {
        float s = 0.f, l = 0.f;
        #pragma unroll
        for (int i = 0; i < THREADS / 32; ++i) { s += red[0][i]; l += red[1][i]; }
        atomicAdd(&g_acc[0], (double)s);
        atomicAdd(&g_acc[1], (double)l);
    }
}

__global__ void ssim_finish_kernel(float* __restrict__ out) {
    double ssim_mean = g_acc[0] / ((double)NIMG * OW * OH);
    double l1_mean   = g_acc[1] / ((double)NIMG * IW * IH);
    out[0] = (float)(0.5 * ssim_mean + 1.0 * l1_mean);
}

extern "C" void kernel_launch(void* const* d_in, const int* in_sizes, int n_in,
                              void* d_out, int out_size) {
    const float* X = (const float*)d_in[0];
    const float* Y = (const float*)d_in[1];
    (void)in_sizes; (void)n_in; (void)out_size;

    // Raise dynamic SMEM cap (idempotent, no allocation; safe under capture).
    cudaFuncSetAttribute(ssim_main_kernel,
                         cudaFuncAttributeMaxDynamicSharedMemorySize, SMEM_BYTES);

    ssim_init_kernel<<<1, 1>>>();
    dim3 grid(IW / TW, IH / TH, NIMG);  // (8, 32, 32) = 8192 blocks
    ssim_main_kernel<<<grid, THREADS, SMEM_BYTES>>>(X, Y);
    ssim_finish_kernel<<<1, 1>>>((float*)d_out);
}

// round 4
// speedup vs baseline: 2.7293x; 2.3914x over previous
#include <cuda_runtime.h>
#include <cstdint>

// ---------------------------------------------------------------------------
// SSIM + L1 fused loss, GB300 sm_103a — round 4: two-pass separable pipeline.
// Pass A (vertical): per-thread column, global->registers, 9-slot ring of 5
//   maps (all imm-FFMA), emit 9-row v-stage to SMEM (5 STS/elem, 0 LDS).
// Pass B (horizontal): thread owns 9 consecutive output cols; 17 loads/map
//   amortized over 9 outputs (~38 B/output LDS), 45 imm-FFMA/output.
// Stage height 9 => ring slots static, single small loop body (I$-friendly).
// v-buffer stride 161 (== 1 mod 32) => provably conflict-free LDS/STS.
// ---------------------------------------------------------------------------

#define IW 1024
#define IH 1024
#define OWID 1016          // valid output dim (VALID 9x9 conv)
#define NIMG 32
#define TW 152             // output cols owned per block
#define THREADS 160        // = loaded cols per block (TW + 8 halo)
#define RB 72              // output rows per block = 8 stages x 9
#define NSTG_MAX 8
#define VSTRIDE 161        // floats per v row (161 % 32 == 1 -> conflict-free)
#define VPLANE 1464        // floats per map plane (9*161=1449, +15 pad)

// Gaussian taps, sigma=1.5, normalized (exact separable form of reference w).
constexpr double E0 = 0.02856550;   // exp(-32/9)
constexpr double E1 = 0.13533528;   // exp(-2)
constexpr double E2 = 0.41111229;   // exp(-8/9)
constexpr double E3 = 0.80073740;   // exp(-2/9)
constexpr double GS = 1.0 + 2.0 * (E0 + E1 + E2 + E3);

__device__ constexpr float G[9] = {
    (float)(E0 / GS), (float)(E1 / GS), (float)(E2 / GS), (float)(E3 / GS),
    (float)(1.0 / GS),
    (float)(E3 / GS), (float)(E2 / GS), (float)(E1 / GS), (float)(E0 / GS)
};

__device__ double g_acc[2];  // [0] = sum(1 - S), [1] = sum |x - y|

__global__ void ssim_init_kernel() { g_acc[0] = 0.0; g_acc[1] = 0.0; }

__global__ __launch_bounds__(THREADS, 3) void ssim_main_kernel(
    const float* __restrict__ X, const float* __restrict__ Y) {
    __shared__ float vbuf[5 * VPLANE];      // 29.3 KB: ux,uy,uxx,uyy,uxy planes
    __shared__ float red[2][THREADS / 32];

    const int t   = threadIdx.x;
    const int tx  = blockIdx.x;   // 0..6
    const int ty  = blockIdx.y;   // 0..14
    const int img = blockIdx.z;   // 0..31
    const int ix0 = tx * TW;
    const int iy0 = ty * RB;
    const size_t base = (size_t)img * IW * IH;
    const float* __restrict__ px = X + base + (size_t)iy0 * IW + (ix0 + t);
    const float* __restrict__ py = Y + base + (size_t)iy0 * IW + (ix0 + t);

    const int  gx      = ix0 + t;
    const bool colin   = gx < IW;
    const bool own_col = colin && (t < TW);

    // Vertical ring accumulators: slot = output_row mod 9.
    float ax[9] = {}, ay[9] = {}, axx[9] = {}, ayy[9] = {}, axy[9] = {};
    float ssim = 0.f, l1 = 0.f;

    // ---- priming: input rows 0..7 (gy always < IH since iy0 <= 1008) ------
    #pragma unroll
    for (int p = 0; p < 8; ++p) {
        float x = colin ? px[p * IW] : 0.f;
        float y = colin ? py[p * IW] : 0.f;
        if (own_col) l1 += fabsf(x - y);
        float xx = x * x, yy = y * y, xy = x * y;
        #pragma unroll
        for (int j = 0; j <= p; ++j) {
            const int sl = (p - j) % 9;          // compile-time constant
            ax [sl] += G[j] * x;
            ay [sl] += G[j] * y;
            axx[sl] += G[j] * xx;
            ayy[sl] += G[j] * yy;
            axy[sl] += G[j] * xy;
        }
    }

    const int vrows = (OWID - iy0 < RB) ? (OWID - iy0) : RB;  // valid out rows
    const int nst   = (vrows + 8) / 9;

    // Pass-B thread mapping: row = t % 9, col-group = t / 9 (9 cols each).
    const int brow = t % 9;
    const int bcg  = t / 9;
    const float* vrd = vbuf + brow * VSTRIDE + bcg * 9;
    const int  orow_base = brow;                 // + 9*s per stage
    const bool lc_ok[9] = {  // local col < TW && global col < OWID, per cc
        (bcg * 9 + 0) < TW && (ix0 + bcg * 9 + 0) < OWID,
        (bcg * 9 + 1) < TW && (ix0 + bcg * 9 + 1) < OWID,
        (bcg * 9 + 2) < TW && (ix0 + bcg * 9 + 2) < OWID,
        (bcg * 9 + 3) < TW && (ix0 + bcg * 9 + 3) < OWID,
        (bcg * 9 + 4) < TW && (ix0 + bcg * 9 + 4) < OWID,
        (bcg * 9 + 5) < TW && (ix0 + bcg * 9 + 5) < OWID,
        (bcg * 9 + 6) < TW && (ix0 + bcg * 9 + 6) < OWID,
        (bcg * 9 + 7) < TW && (ix0 + bcg * 9 + 7) < OWID,
        (bcg * 9 + 8) < TW && (ix0 + bcg * 9 + 8) < OWID };

    for (int s = 0; s < nst; ++s) {
        // ---- Pass A: consume input rows 9s+8 .. 9s+16, emit v rows 0..8 ---
        const float* pxs = px + (9 * s + 8) * IW;
        const float* pys = py + (9 * s + 8) * IW;
        const int gy0 = iy0 + 9 * s + 8;
        #pragma unroll
        for (int i = 0; i < 9; ++i) {
            const bool rin = (gy0 + i) < IH;
            const bool ld  = rin && colin;
            float x = ld ? pxs[i * IW] : 0.f;
            float y = ld ? pys[i * IW] : 0.f;
            if (own_col && rin && (9 * s + 8 + i) < RB) l1 += fabsf(x - y);
            float xx = x * x, yy = y * y, xy = x * y;
            #pragma unroll
            for (int j = 0; j < 9; ++j) {
                const int sl = (8 + i - j) % 9;  // compile-time constant
                ax [sl] += G[j] * x;
                ay [sl] += G[j] * y;
                axx[sl] += G[j] * xx;
                ayy[sl] += G[j] * yy;
                axy[sl] += G[j] * xy;
            }
            // output row o = 9s+i is complete in slot i: emit + clear.
            vbuf[0 * VPLANE + i * VSTRIDE + t] = ax [i];
            vbuf[1 * VPLANE + i * VSTRIDE + t] = ay [i];
            vbuf[2 * VPLANE + i * VSTRIDE + t] = axx[i];
            vbuf[3 * VPLANE + i * VSTRIDE + t] = ayy[i];
            vbuf[4 * VPLANE + i * VSTRIDE + t] = axy[i];
            ax[i] = 0.f; ay[i] = 0.f; axx[i] = 0.f; ayy[i] = 0.f; axy[i] = 0.f;
        }
        __syncthreads();

        // ---- Pass B: horizontal conv, 9 cols per thread -------------------
        float o0[9], o1[9], o2[9], o3[9], o4[9];
        #define HMAP(M, OUT)                                                  \
        {                                                                     \
            float in[17];                                                     \
            _Pragma("unroll")                                                 \
            for (int k = 0; k < 17; ++k) in[k] = vrd[(M) * VPLANE + k];       \
            _Pragma("unroll")                                                 \
            for (int c = 0; c < 9; ++c) {                                     \
                float a = G[0] * in[c];                                       \
                _Pragma("unroll")                                             \
                for (int k = 1; k < 9; ++k) a += G[k] * in[c + k];            \
                OUT[c] = a;                                                   \
            }                                                                 \
        }
        HMAP(0, o0) HMAP(1, o1) HMAP(2, o2) HMAP(3, o3) HMAP(4, o4)
        #undef HMAP

        const bool rowok = (9 * s + orow_base) < vrows;
        constexpr float C1 = 0.0004f;   // (0.01*2)^2
        constexpr float C2 = 0.0036f;   // (0.03*2)^2
        #pragma unroll
        for (int c = 0; c < 9; ++c) {
            if (rowok && lc_ok[c]) {
                float ux = o0[c], uy = o1[c];
                float uxx = o2[c], uyy = o3[c], uxy = o4[c];
                float vx  = uxx - ux * ux;
                float vy  = uyy - uy * uy;
                float vxy = uxy - ux * uy;
                float A1v = 2.f * ux * uy + C1;
                float A2v = 2.f * vxy + C2;
                float B1v = ux * ux + uy * uy + C1;
                float B2v = vx + vy + C2;
                ssim += 1.f - __fdividef(A1v * A2v, B1v * B2v);
            }
        }
        __syncthreads();   // v-buffer free for next stage's pass A
    }

    // ---- Block reduction, one double atomic pair per block ----------------
    #pragma unroll
    for (int off = 16; off; off >>= 1) {
        ssim += __shfl_down_sync(0xffffffffu, ssim, off);
        l1   += __shfl_down_sync(0xffffffffu, l1,   off);
    }
    const int w = t >> 5;
    if ((t & 31) == 0) { red[0][w] = ssim; red[1][w] = l1; }
    __syncthreads();
    if (t == 0) {
        float sa = 0.f, la = 0.f;
        #pragma unroll
        for (int i = 0; i < THREADS / 32; ++i) { sa += red[0][i]; la += red[1][i]; }
        atomicAdd(&g_acc[0], (double)sa);
        atomicAdd(&g_acc[1], (double)la);
    }
}

__global__ void ssim_finish_kernel(float* __restrict__ out) {
    double ssim_mean = g_acc[0] / ((double)NIMG * OWID * OWID);
    double l1_mean   = g_acc[1] / ((double)NIMG * IW * IH);
    out[0] = (float)(0.5 * ssim_mean + 1.0 * l1_mean);
}

extern "C" void kernel_launch(void* const* d_in, const int* in_sizes, int n_in,
                              void* d_out, int out_size) {
    const float* X = (const float*)d_in[0];
    const float* Y = (const float*)d_in[1];
    (void)in_sizes; (void)n_in; (void)out_size;

    ssim_init_kernel<<<1, 1>>>();
    dim3 grid((OWID + TW - 1) / TW,   // 7
              (OWID + RB - 1) / RB,   // 15
              NIMG);                  // 32  -> 3360 blocks
    ssim_main_kernel<<<grid, THREADS>>>(X, Y);
    ssim_finish_kernel<<<1, 1>>>((float*)d_out);
}

// round 5
// speedup vs baseline: 3.0373x; 1.1128x over previous
#include <cuda_runtime.h>
#include <cstdint>

// ---------------------------------------------------------------------------
// SSIM + L1 fused loss, GB300 sm_103a — round 5: (p,q) basis, 4 conv maps.
// p = x+y, q = x-y:  conv(p),conv(q),conv(p^2),conv(q^2) suffice:
//   4*ux*uy   = P^2 - Q^2          2*(ux^2+uy^2) = P^2 + Q^2
//   4*uxy     = PP - QQ            2*(uxx+uyy)   = PP + QQ
// => A1 = .5(P^2-Q^2)+C1, A2 = .5((PP-QQ)-(P^2-Q^2))+C2,
//    B1 = .5(P^2+Q^2)+C1, B2 = .5((PP+QQ)-(P^2+Q^2))+C2.
// 20% fewer conv FMAs, 1 fewer STS, 20% fewer LDS; |q| gives the L1 term.
// Two-pass pipeline otherwise identical to round 4 (the 194us winner).
// ---------------------------------------------------------------------------

#define IW 1024
#define IH 1024
#define OWID 1016          // valid output dim (VALID 9x9 conv)
#define NIMG 32
#define TW 152             // output cols owned per block
#define THREADS 160        // = loaded cols per block (TW + 8 halo)
#define RB 72              // output rows per block = 8 stages x 9
#define VSTRIDE 161        // floats per v row (161 % 32 == 1 -> conflict-free)
#define VPLANE 1464        // floats per map plane (9*161=1449, +15 pad)

// Gaussian taps, sigma=1.5, normalized (exact separable form of reference w).
constexpr double E0 = 0.02856550;   // exp(-32/9)
constexpr double E1 = 0.13533528;   // exp(-2)
constexpr double E2 = 0.41111229;   // exp(-8/9)
constexpr double E3 = 0.80073740;   // exp(-2/9)
constexpr double GS = 1.0 + 2.0 * (E0 + E1 + E2 + E3);

__device__ constexpr float G[9] = {
    (float)(E0 / GS), (float)(E1 / GS), (float)(E2 / GS), (float)(E3 / GS),
    (float)(1.0 / GS),
    (float)(E3 / GS), (float)(E2 / GS), (float)(E1 / GS), (float)(E0 / GS)
};

__device__ double g_acc[2];  // [0] = sum(1 - S), [1] = sum |x - y|

__global__ void ssim_init_kernel() { g_acc[0] = 0.0; g_acc[1] = 0.0; }

__global__ __launch_bounds__(THREADS, 3) void ssim_main_kernel(
    const float* __restrict__ X, const float* __restrict__ Y) {
    __shared__ float vbuf[4 * VPLANE];      // 23.4 KB: P, Q, PP, QQ planes
    __shared__ float red[2][THREADS / 32];

    const int t   = threadIdx.x;
    const int tx  = blockIdx.x;   // 0..6
    const int ty  = blockIdx.y;   // 0..14
    const int img = blockIdx.z;   // 0..31
    const int ix0 = tx * TW;
    const int iy0 = ty * RB;
    const size_t base = (size_t)img * IW * IH;
    const float* __restrict__ px = X + base + (size_t)iy0 * IW + (ix0 + t);
    const float* __restrict__ py = Y + base + (size_t)iy0 * IW + (ix0 + t);

    const int  gx      = ix0 + t;
    const bool colin   = gx < IW;
    const bool own_col = colin && (t < TW);

    // Vertical ring accumulators: slot = output_row mod 9.  4 maps.
    float ap[9] = {}, aq[9] = {}, app[9] = {}, aqq[9] = {};
    float ssim = 0.f, l1 = 0.f;

    // ---- priming: input rows 0..7 (gy always < IH since iy0 <= 1008) ------
    #pragma unroll
    for (int prow = 0; prow < 8; ++prow) {
        float x = colin ? px[prow * IW] : 0.f;
        float y = colin ? py[prow * IW] : 0.f;
        float p = x + y, q = x - y;
        if (own_col) l1 += fabsf(q);
        float pp = p * p, qq = q * q;
        #pragma unroll
        for (int j = 0; j <= prow; ++j) {
            const int sl = (prow - j) % 9;       // compile-time constant
            ap [sl] += G[j] * p;
            aq [sl] += G[j] * q;
            app[sl] += G[j] * pp;
            aqq[sl] += G[j] * qq;
        }
    }

    const int vrows = (OWID - iy0 < RB) ? (OWID - iy0) : RB;  // valid out rows
    const int nst   = (vrows + 8) / 9;

    // Pass-B thread mapping: row = t % 9, col-group = t / 9 (9 cols each).
    const int brow = t % 9;
    const int bcg  = t / 9;
    const float* vrd = vbuf + brow * VSTRIDE + bcg * 9;
    const int  orow_base = brow;
    const bool lc_ok[9] = {  // local col < TW && global col < OWID, per cc
        (bcg * 9 + 0) < TW && (ix0 + bcg * 9 + 0) < OWID,
        (bcg * 9 + 1) < TW && (ix0 + bcg * 9 + 1) < OWID,
        (bcg * 9 + 2) < TW && (ix0 + bcg * 9 + 2) < OWID,
        (bcg * 9 + 3) < TW && (ix0 + bcg * 9 + 3) < OWID,
        (bcg * 9 + 4) < TW && (ix0 + bcg * 9 + 4) < OWID,
        (bcg * 9 + 5) < TW && (ix0 + bcg * 9 + 5) < OWID,
        (bcg * 9 + 6) < TW && (ix0 + bcg * 9 + 6) < OWID,
        (bcg * 9 + 7) < TW && (ix0 + bcg * 9 + 7) < OWID,
        (bcg * 9 + 8) < TW && (ix0 + bcg * 9 + 8) < OWID };

    for (int s = 0; s < nst; ++s) {
        // ---- Pass A: consume input rows 9s+8 .. 9s+16, emit v rows 0..8 ---
        const float* pxs = px + (9 * s + 8) * IW;
        const float* pys = py + (9 * s + 8) * IW;
        const int gy0 = iy0 + 9 * s + 8;
        #pragma unroll
        for (int i = 0; i < 9; ++i) {
            const bool rin = (gy0 + i) < IH;
            const bool ld  = rin && colin;
            float x = ld ? pxs[i * IW] : 0.f;
            float y = ld ? pys[i * IW] : 0.f;
            float p = x + y, q = x - y;
            if (own_col && rin && (9 * s + 8 + i) < RB) l1 += fabsf(q);
            float pp = p * p, qq = q * q;
            #pragma unroll
            for (int j = 0; j < 9; ++j) {
                const int sl = (8 + i - j) % 9;  // compile-time constant
                ap [sl] += G[j] * p;
                aq [sl] += G[j] * q;
                app[sl] += G[j] * pp;
                aqq[sl] += G[j] * qq;
            }
            // output row o = 9s+i is complete in slot i: emit + clear.
            vbuf[0 * VPLANE + i * VSTRIDE + t] = ap [i];
            vbuf[1 * VPLANE + i * VSTRIDE + t] = aq [i];
            vbuf[2 * VPLANE + i * VSTRIDE + t] = app[i];
            vbuf[3 * VPLANE + i * VSTRIDE + t] = aqq[i];
            ap[i] = 0.f; aq[i] = 0.f; app[i] = 0.f; aqq[i] = 0.f;
        }
        __syncthreads();

        // ---- Pass B: horizontal conv, 9 cols per thread, 4 maps -----------
        float oP[9], oQ[9], oPP[9], oQQ[9];
        #define HMAP(M, OUT)                                                  \
        {                                                                     \
            float in[17];                                                     \
            _Pragma("unroll")                                                 \
            for (int k = 0; k < 17; ++k) in[k] = vrd[(M) * VPLANE + k];       \
            _Pragma("unroll")                                                 \
            for (int c = 0; c < 9; ++c) {                                     \
                float a = G[0] * in[c];                                       \
                _Pragma("unroll")                                             \
                for (int k = 1; k < 9; ++k) a += G[k] * in[c + k];            \
                OUT[c] = a;                                                   \
            }                                                                 \
        }
        HMAP(0, oP) HMAP(1, oQ) HMAP(2, oPP) HMAP(3, oQQ)
        #undef HMAP

        const bool rowok = (9 * s + orow_base) < vrows;
        constexpr float C1 = 0.0004f;   // (0.01*2)^2
        constexpr float C2 = 0.0036f;   // (0.03*2)^2
        #pragma unroll
        for (int c = 0; c < 9; ++c) {
            if (rowok && lc_ok[c]) {
                float P = oP[c], Q = oQ[c], PP = oPP[c], QQ = oQQ[c];
                float sp  = P * P;
                float sq  = Q * Q;
                float dmu = sp - sq;            // 4*ux*uy
                float smu = sp + sq;            // 2*(ux^2+uy^2)
                float dv  = (PP - QQ) - dmu;    // 4*vxy
                float sv  = (PP + QQ) - smu;    // 2*(vx+vy)
                float A1v = 0.5f * dmu + C1;
                float A2v = 0.5f * dv  + C2;
                float B1v = 0.5f * smu + C1;
                float B2v = 0.5f * sv  + C2;
                ssim += 1.f - __fdividef(A1v * A2v, B1v * B2v);
            }
        }
        __syncthreads();   // v-buffer free for next stage's pass A
    }

    // ---- Block reduction, one double atomic pair per block ----------------
    #pragma unroll
    for (int off = 16; off; off >>= 1) {
        ssim += __shfl_down_sync(0xffffffffu, ssim, off);
        l1   += __shfl_down_sync(0xffffffffu, l1,   off);
    }
    const int w = t >> 5;
    if ((t & 31) == 0) { red[0][w] = ssim; red[1][w] = l1; }
    __syncthreads();
    if (t == 0) {
        float sa = 0.f, la = 0.f;
        #pragma unroll
        for (int i = 0; i < THREADS / 32; ++i) { sa += red[0][i]; la += red[1][i]; }
        atomicAdd(&g_acc[0], (double)sa);
        atomicAdd(&g_acc[1], (double)la);
    }
}

__global__ void ssim_finish_kernel(float* __restrict__ out) {
    double ssim_mean = g_acc[0] / ((double)NIMG * OWID * OWID);
    double l1_mean   = g_acc[1] / ((double)NIMG * IW * IH);
    out[0] = (float)(0.5 * ssim_mean + 1.0 * l1_mean);
}

extern "C" void kernel_launch(void* const* d_in, const int* in_sizes, int n_in,
                              void* d_out, int out_size) {
    const float* X = (const float*)d_in[0];
    const float* Y = (const float*)d_in[1];
    (void)in_sizes; (void)n_in; (void)out_size;

    ssim_init_kernel<<<1, 1>>>();
    dim3 grid((OWID + TW - 1) / TW,   // 7
              (OWID + RB - 1) / RB,   // 15
              NIMG);                  // 32  -> 3360 blocks
    ssim_main_kernel<<<grid, THREADS>>>(X, Y);
    ssim_finish_kernel<<<1, 1>>>((float*)d_out);
}

// round 6
// speedup vs baseline: 3.2127x; 1.0577x over previous
#include <cuda_runtime.h>
#include <cstdint>

// ---------------------------------------------------------------------------
// SSIM + L1 fused loss, GB300 sm_103a — round 6: batched divisions.
// Identical two-pass (p,q)-basis pipeline to round 5 (174us), except the
// epilogue: per-pixel S = n/d fractions are combined pairwise
// (S1+S2 = (n1*d2+n2*d1)/(d1*d2)) into groups {0-3} and {4-8}, cutting
// MUFU.RCP (rt_SMSP=8, the widest pipe term) from 9 to 2 per 9 outputs.
// "1 - S" is recovered via an exact integer count of valid pixels.
// ---------------------------------------------------------------------------

#define IW 1024
#define IH 1024
#define OWID 1016          // valid output dim (VALID 9x9 conv)
#define NIMG 32
#define TW 152             // output cols owned per block
#define THREADS 160        // = loaded cols per block (TW + 8 halo)
#define RB 72              // output rows per block = 8 stages x 9
#define VSTRIDE 161        // floats per v row (161 % 32 == 1 -> conflict-free)
#define VPLANE 1464        // floats per map plane (9*161=1449, +15 pad)

// Gaussian taps, sigma=1.5, normalized (exact separable form of reference w).
constexpr double E0 = 0.02856550;   // exp(-32/9)
constexpr double E1 = 0.13533528;   // exp(-2)
constexpr double E2 = 0.41111229;   // exp(-8/9)
constexpr double E3 = 0.80073740;   // exp(-2/9)
constexpr double GS = 1.0 + 2.0 * (E0 + E1 + E2 + E3);

__device__ constexpr float G[9] = {
    (float)(E0 / GS), (float)(E1 / GS), (float)(E2 / GS), (float)(E3 / GS),
    (float)(1.0 / GS),
    (float)(E3 / GS), (float)(E2 / GS), (float)(E1 / GS), (float)(E0 / GS)
};

__device__ double g_acc[2];  // [0] = sum(1 - S), [1] = sum |x - y|

__global__ void ssim_init_kernel() { g_acc[0] = 0.0; g_acc[1] = 0.0; }

__global__ __launch_bounds__(THREADS, 3) void ssim_main_kernel(
    const float* __restrict__ X, const float* __restrict__ Y) {
    __shared__ float vbuf[4 * VPLANE];      // 23.4 KB: P, Q, PP, QQ planes
    __shared__ float red[2][THREADS / 32];

    const int t   = threadIdx.x;
    const int tx  = blockIdx.x;   // 0..6
    const int ty  = blockIdx.y;   // 0..14
    const int img = blockIdx.z;   // 0..31
    const int ix0 = tx * TW;
    const int iy0 = ty * RB;
    const size_t base = (size_t)img * IW * IH;
    const float* __restrict__ px = X + base + (size_t)iy0 * IW + (ix0 + t);
    const float* __restrict__ py = Y + base + (size_t)iy0 * IW + (ix0 + t);

    const int  gx      = ix0 + t;
    const bool colin   = gx < IW;
    const bool own_col = colin && (t < TW);

    // Vertical ring accumulators: slot = output_row mod 9.  4 maps.
    float ap[9] = {}, aq[9] = {}, app[9] = {}, aqq[9] = {};
    float Ssum = 0.f, l1 = 0.f;
    int   vcnt = 0;                      // number of valid pixels accumulated

    // ---- priming: input rows 0..7 (gy always < IH since iy0 <= 1008) ------
    #pragma unroll
    for (int prow = 0; prow < 8; ++prow) {
        float x = colin ? px[prow * IW] : 0.f;
        float y = colin ? py[prow * IW] : 0.f;
        float p = x + y, q = x - y;
        if (own_col) l1 += fabsf(q);
        float pp = p * p, qq = q * q;
        #pragma unroll
        for (int j = 0; j <= prow; ++j) {
            const int sl = (prow - j) % 9;       // compile-time constant
            ap [sl] += G[j] * p;
            aq [sl] += G[j] * q;
            app[sl] += G[j] * pp;
            aqq[sl] += G[j] * qq;
        }
    }

    const int vrows = (OWID - iy0 < RB) ? (OWID - iy0) : RB;  // valid out rows
    const int nst   = (vrows + 8) / 9;

    // Pass-B thread mapping: row = t % 9, col-group = t / 9 (9 cols each).
    const int brow = t % 9;
    const int bcg  = t / 9;
    const float* vrd = vbuf + brow * VSTRIDE + bcg * 9;
    bool lc_ok[9];
    int  n_lc = 0;
    #pragma unroll
    for (int c = 0; c < 9; ++c) {
        lc_ok[c] = (bcg * 9 + c) < TW && (ix0 + bcg * 9 + c) < OWID;
        n_lc += lc_ok[c] ? 1 : 0;
    }

    for (int s = 0; s < nst; ++s) {
        // ---- Pass A: consume input rows 9s+8 .. 9s+16, emit v rows 0..8 ---
        const float* pxs = px + (9 * s + 8) * IW;
        const float* pys = py + (9 * s + 8) * IW;
        const int gy0 = iy0 + 9 * s + 8;
        #pragma unroll
        for (int i = 0; i < 9; ++i) {
            const bool rin = (gy0 + i) < IH;
            const bool ld  = rin && colin;
            float x = ld ? pxs[i * IW] : 0.f;
            float y = ld ? pys[i * IW] : 0.f;
            float p = x + y, q = x - y;
            if (own_col && rin && (9 * s + 8 + i) < RB) l1 += fabsf(q);
            float pp = p * p, qq = q * q;
            #pragma unroll
            for (int j = 0; j < 9; ++j) {
                const int sl = (8 + i - j) % 9;  // compile-time constant
                ap [sl] += G[j] * p;
                aq [sl] += G[j] * q;
                app[sl] += G[j] * pp;
                aqq[sl] += G[j] * qq;
            }
            // output row o = 9s+i is complete in slot i: emit + clear.
            vbuf[0 * VPLANE + i * VSTRIDE + t] = ap [i];
            vbuf[1 * VPLANE + i * VSTRIDE + t] = aq [i];
            vbuf[2 * VPLANE + i * VSTRIDE + t] = app[i];
            vbuf[3 * VPLANE + i * VSTRIDE + t] = aqq[i];
            ap[i] = 0.f; aq[i] = 0.f; app[i] = 0.f; aqq[i] = 0.f;
        }
        __syncthreads();

        // ---- Pass B: horizontal conv, 9 cols per thread, 4 maps -----------
        float oP[9], oQ[9], oPP[9], oQQ[9];
        #define HMAP(M, OUT)                                                  \
        {                                                                     \
            float in[17];                                                     \
            _Pragma("unroll")                                                 \
            for (int k = 0; k < 17; ++k) in[k] = vrd[(M) * VPLANE + k];       \
            _Pragma("unroll")                                                 \
            for (int c = 0; c < 9; ++c) {                                     \
                float a = G[0] * in[c];                                       \
                _Pragma("unroll")                                             \
                for (int k = 1; k < 9; ++k) a += G[k] * in[c + k];            \
                OUT[c] = a;                                                   \
            }                                                                 \
        }
        HMAP(0, oP) HMAP(1, oQ) HMAP(2, oPP) HMAP(3, oQQ)
        #undef HMAP

        const bool rowok = (9 * s + brow) < vrows;
        constexpr float C1 = 0.0004f;   // (0.01*2)^2
        constexpr float C2 = 0.0036f;   // (0.03*2)^2

        // Per-pixel fractions n/d, masked invalid -> (0, 1).
        float nf[9], df[9];
        #pragma unroll
        for (int c = 0; c < 9; ++c) {
            float P = oP[c], Q = oQ[c], PP = oPP[c], QQ = oQQ[c];
            float sp  = P * P;
            float sq  = Q * Q;
            float dmu = sp - sq;            // 4*ux*uy
            float smu = sp + sq;            // 2*(ux^2+uy^2)
            float dv  = (PP - QQ) - dmu;    // 4*vxy
            float sv  = (PP + QQ) - smu;    // 2*(vx+vy)
            float A1v = 0.5f * dmu + C1;
            float A2v = 0.5f * dv  + C2;
            float B1v = 0.5f * smu + C1;
            float B2v = 0.5f * sv  + C2;
            bool ok = rowok && lc_ok[c];
            nf[c] = ok ? A1v * A2v : 0.f;
            df[c] = ok ? B1v * B2v : 1.f;
        }
        vcnt += rowok ? n_lc : 0;

        // Combine {0,1,2,3}: 1 division for 4 pixels.
        {
            float d01 = df[0] * df[1];
            float n01 = nf[0] * df[1] + nf[1] * df[0];
            float d23 = df[2] * df[3];
            float n23 = nf[2] * df[3] + nf[3] * df[2];
            float dG  = d01 * d23;
            float nG  = n01 * d23 + n23 * d01;
            Ssum += __fdividef(nG, dG);
        }
        // Combine {4,5,6,7,8}: 1 division for 5 pixels.
        {
            float d45 = df[4] * df[5];
            float n45 = nf[4] * df[5] + nf[5] * df[4];
            float d67 = df[6] * df[7];
            float n67 = nf[6] * df[7] + nf[7] * df[6];
            float d47 = d45 * d67;
            float n47 = n45 * d67 + n67 * d45;
            float dG  = d47 * df[8];
            float nG  = n47 * df[8] + nf[8] * d47;
            Ssum += __fdividef(nG, dG);
        }
        __syncthreads();   // v-buffer free for next stage's pass A
    }

    // ssim contribution = sum(1 - S) = vcnt - Ssum.
    float ssim = (float)vcnt - Ssum;

    // ---- Block reduction, one double atomic pair per block ----------------
    #pragma unroll
    for (int off = 16; off; off >>= 1) {
        ssim += __shfl_down_sync(0xffffffffu, ssim, off);
        l1   += __shfl_down_sync(0xffffffffu, l1,   off);
    }
    const int w = t >> 5;
    if ((t & 31) == 0) { red[0][w] = ssim; red[1][w] = l1; }
    __syncthreads();
    if (t == 0) {
        float sa = 0.f, la = 0.f;
        #pragma unroll
        for (int i = 0; i < THREADS / 32; ++i) { sa += red[0][i]; la += red[1][i]; }
        atomicAdd(&g_acc[0], (double)sa);
        atomicAdd(&g_acc[1], (double)la);
    }
}

__global__ void ssim_finish_kernel(float* __restrict__ out) {
    double ssim_mean = g_acc[0] / ((double)NIMG * OWID * OWID);
    double l1_mean   = g_acc[1] / ((double)NIMG * IW * IH);
    out[0] = (float)(0.5 * ssim_mean + 1.0 * l1_mean);
}

extern "C" void kernel_launch(void* const* d_in, const int* in_sizes, int n_in,
                              void* d_out, int out_size) {
    const float* X = (const float*)d_in[0];
    const float* Y = (const float*)d_in[1];
    (void)in_sizes; (void)n_in; (void)out_size;

    ssim_init_kernel<<<1, 1>>>();
    dim3 grid((OWID + TW - 1) / TW,   // 7
              (OWID + RB - 1) / RB,   // 15
              NIMG);                  // 32  -> 3360 blocks
    ssim_main_kernel<<<grid, THREADS>>>(X, Y);
    ssim_finish_kernel<<<1, 1>>>((float*)d_out);
}